// round 12
// baseline (speedup 1.0000x reference)
#include <cuda_runtime.h>
#include <cuda_fp16.h>
#include <math.h>
#include <stdint.h>

// ---------------- problem constants ----------------
#define N_ROWS 8192
#define DIM    128
#define NCLS   1000
#define EPSL   1e-10
#define NCHUNK 16               // j-chunks; JT = 4 j-tiles per CTA
#define JT     4

// ---------------- scratch (device globals; no allocations) ------------------
__device__ __align__(16) float  g_f1[N_ROWS * DIM];   // normalized fs (fp32)
__device__ __align__(16) float  g_f2[N_ROWS * DIM];   // normalized ft (fp32)
__device__ __align__(16) __half g_h1[N_ROWS * DIM];   // fp16 normalized fs
__device__ __align__(16) __half g_h2[N_ROWS * DIM];   // fp16 normalized ft

__device__ float g_part[NCHUNK * N_ROWS * 2];  // per-chunk (S1,S2)
__device__ float g_S[N_ROWS * 2];              // combined (S1,S2)
__device__ float g_pos[N_ROWS * 3];            // L, P1, P2
__device__ int   g_npos[N_ROWS];
__device__ float g_jsd[N_ROWS];
__device__ unsigned g_ctr = 0;                 // last-block election counter

// ---------------- fast exp (FMA/ALU pipes only) ------------------------------
__device__ __forceinline__ float fexp2(float y) {
    float z = y + 12582912.0f;                 // round-to-nearest integer
    int   i = __float_as_int(z) - 0x4B400000;
    float f = y - (z - 12582912.0f);           // frac in [-0.5, 0.5]
    float p = 0.0013333558f;
    p = fmaf(p, f, 0.0096181291f);
    p = fmaf(p, f, 0.0555041087f);
    p = fmaf(p, f, 0.2402265070f);
    p = fmaf(p, f, 0.6931471806f);
    p = fmaf(p, f, 1.0f);
    return p * __int_as_float((i + 127) << 23);
}
__device__ __forceinline__ float fexp10s(float c) {   // exp((c-1)*10)
    return fexp2(fmaf(c, 14.4269504089f, -14.4269504089f));
}
__device__ __forceinline__ float fexpe(float x) {     // exp(x)
    return fexp2(x * 1.44269504089f);
}

// ---------------- PTX helpers -----------------------------------------------
__device__ __forceinline__ uint32_t smem_u32(const void* p) {
    uint32_t a;
    asm("{ .reg .u64 t; cvta.to.shared.u64 t, %1; cvt.u32.u64 %0, t; }"
        : "=r"(a) : "l"(p));
    return a;
}
__device__ __forceinline__ void cpa16(uint32_t s, const void* g) {
    asm volatile("cp.async.cg.shared.global [%0], [%1], 16;"
                 :: "r"(s), "l"(g) : "memory");
}
__device__ __forceinline__ void cpa_commit() {
    asm volatile("cp.async.commit_group;" ::: "memory");
}
__device__ __forceinline__ void cpa_wait0() {
    asm volatile("cp.async.wait_group 0;" ::: "memory");
}
__device__ __forceinline__ uint32_t lds32(uint32_t a) {
    uint32_t v;
    asm volatile("ld.shared.b32 %0, [%1];" : "=r"(v) : "r"(a));
    return v;
}
__device__ __forceinline__ void mma16816(float c[4], const uint32_t a[4],
                                         const uint32_t b[2]) {
    asm volatile(
        "mma.sync.aligned.m16n8k16.row.col.f32.f16.f16.f32 "
        "{%0,%1,%2,%3}, {%4,%5,%6,%7}, {%8,%9}, {%0,%1,%2,%3};"
        : "+f"(c[0]), "+f"(c[1]), "+f"(c[2]), "+f"(c[3])
        : "r"(a[0]), "r"(a[1]), "r"(a[2]), "r"(a[3]), "r"(b[0]), "r"(b[1]));
}

// ---------------- K_A: fused normalize(fs) | normalize(ft) | JSD -------------
__device__ __forceinline__ void norm_rows(const float* __restrict__ in,
                                          float* __restrict__ fout,
                                          __half* __restrict__ hout,
                                          int w, int lane) {
    float4 v = *(const float4*)(in + (size_t)w * DIM + lane * 4);
    float ss = v.x * v.x + v.y * v.y + v.z * v.z + v.w * v.w;
    #pragma unroll
    for (int s = 16; s; s >>= 1) ss += __shfl_xor_sync(0xffffffffu, ss, s);
    float inv = 1.0f / fmaxf(sqrtf(ss), 1e-12f);
    float x[4] = {v.x * inv, v.y * inv, v.z * inv, v.w * inv};
    *(float4*)(fout + (size_t)w * DIM + lane * 4) = make_float4(x[0], x[1], x[2], x[3]);

    uint32_t p[2] = {0, 0};
    #pragma unroll
    for (int i = 0; i < 4; i++) {
        __half h = __float2half_rn(x[i]);
        p[i >> 1] |= (uint32_t)__half_as_ushort(h) << (16 * (i & 1));
    }
    size_t base = (size_t)w * DIM + lane * 4;
    *(uint2*)((char*)hout + base * 2) = make_uint2(p[0], p[1]);
}

__global__ __launch_bounds__(256) void k_prep(const float* __restrict__ fs,
                                              const float* __restrict__ ft,
                                              const float* __restrict__ ls,
                                              const float* __restrict__ lt) {
    int b = blockIdx.x;
    if (b < 2048) {
        // normalization: blocks 0..1023 -> fs, 1024..2047 -> ft
        int w    = ((b & 1023) * 256 + threadIdx.x) >> 5;
        int lane = threadIdx.x & 31;
        if (b < 1024) norm_rows(fs, g_f1, g_h1, w, lane);
        else          norm_rows(ft, g_f2, g_h2, w, lane);
        return;
    }
    // JSD: one block per row, SINGLE pass over logits.
    // kl_st + kl_ts = sum (pt - ps)(zt - zs) = U/St - V/Ss
    int r = b - 2048;
    const float* zs = ls + (size_t)r * NCLS;
    const float* zt = lt + (size_t)r * NCLS;
    int tid = threadIdx.x;

    float Ss = 0.f, St = 0.f, U = 0.f, V = 0.f;
    for (int c = tid; c < NCLS; c += 256) {
        float a = zs[c], bb = zt[c];
        float es = fexpe(a), et = fexpe(bb);
        float d = bb - a;
        Ss += es;
        St += et;
        U = fmaf(et, d, U);
        V = fmaf(es, d, V);
    }
    // fused 4-value block reduction (one barrier round)
    __shared__ float sh[4][8];
    int lane = tid & 31, wid = tid >> 5;
    #pragma unroll
    for (int s = 16; s; s >>= 1) {
        Ss += __shfl_xor_sync(0xffffffffu, Ss, s);
        St += __shfl_xor_sync(0xffffffffu, St, s);
        U  += __shfl_xor_sync(0xffffffffu, U, s);
        V  += __shfl_xor_sync(0xffffffffu, V, s);
    }
    if (lane == 0) { sh[0][wid] = Ss; sh[1][wid] = St; sh[2][wid] = U; sh[3][wid] = V; }
    __syncthreads();
    if (tid == 0) {
        float ss2 = 0.f, st2 = 0.f, u2 = 0.f, v2 = 0.f;
        #pragma unroll
        for (int i = 0; i < 8; i++) {
            ss2 += sh[0][i]; st2 += sh[1][i]; u2 += sh[2][i]; v2 += sh[3][i];
        }
        g_jsd[r] = __fdividef(u2, st2) - __fdividef(v2, ss2);
    }
}

// ---------------- K_B: fp16 mma.sync moments GEMM ----------------------------
#define BUF_B  33024                     // 16 * 2064
#define SM_A   0
#define SM_B(s) (BUF_B + (s) * BUF_B)
#define SMEM_GEMM (3 * BUF_B)            // 99072 bytes

__device__ __forceinline__ void load_tile(uint32_t sdst, const char* gsrc, int tid) {
    #pragma unroll
    for (int i = 0; i < 4; i++) {
        int flat = tid + i * 512;
        int r = flat >> 4, gI = flat & 15;
        cpa16(sdst + gI * 2064 + r * 16, gsrc + r * 256 + gI * 16);
    }
}

__global__ __launch_bounds__(512) void k_moments_mma() {
    extern __shared__ __align__(16) char smem[];
    const int tid  = threadIdx.x;
    const int warp = tid >> 5, lane = tid & 31;
    const int g    = lane >> 2, tg = lane & 3;
    const int wm   = warp >> 2, wn = warp & 3;
    const int row0 = blockIdx.y * 128;
    const int chunk = blockIdx.x;

    const uint32_t sb = smem_u32(smem);

    {
        int t0 = chunk * JT;
        load_tile(sb + SM_A, (const char*)g_h1 + (size_t)row0 * 256, tid);
        load_tile(sb + SM_B(0), (const char*)g_h2 + (size_t)t0 * 32768, tid);
        cpa_commit();
        cpa_wait0();
    }
    __syncthreads();

    const uint32_t aByte = (uint32_t)(wm * 32 + g) * 16 + tg * 4;
    const uint32_t bByte = (uint32_t)(wn * 32 + g) * 16 + tg * 4;

    float s1[4] = {0, 0, 0, 0}, s2[4] = {0, 0, 0, 0};

    for (int jt = 0; jt < JT; jt++) {
        const int cur = jt & 1;
        if (jt + 1 < JT) {
            int tn = chunk * JT + jt + 1;
            load_tile(sb + SM_B(1 - cur), (const char*)g_h2 + (size_t)tn * 32768, tid);
            cpa_commit();
        }

        float cacc[2][4][4];
        #pragma unroll
        for (int mt = 0; mt < 2; mt++)
            #pragma unroll
            for (int nt = 0; nt < 4; nt++)
                #pragma unroll
                for (int ci = 0; ci < 4; ci++) cacc[mt][nt][ci] = 0.f;

        const uint32_t aB = sb + SM_A + aByte;
        const uint32_t bB = sb + SM_B(cur) + bByte;

        #pragma unroll
        for (int ks = 0; ks < 8; ks++) {
            const uint32_t c0 = (uint32_t)(2 * ks) * 2064, c1 = c0 + 2064;
            uint32_t af[2][4], bf[4][2];
            #pragma unroll
            for (int mt = 0; mt < 2; mt++) {
                uint32_t ro = mt * 256;
                af[mt][0] = lds32(aB + c0 + ro);
                af[mt][1] = lds32(aB + c0 + ro + 128);
                af[mt][2] = lds32(aB + c1 + ro);
                af[mt][3] = lds32(aB + c1 + ro + 128);
            }
            #pragma unroll
            for (int nt = 0; nt < 4; nt++) {
                uint32_t no = nt * 128;
                bf[nt][0] = lds32(bB + c0 + no);
                bf[nt][1] = lds32(bB + c1 + no);
            }
            #pragma unroll
            for (int mt = 0; mt < 2; mt++)
                #pragma unroll
                for (int nt = 0; nt < 4; nt++)
                    mma16816(cacc[mt][nt], af[mt], bf[nt]);
        }

        // fused epilogue: poly-exp moments
        #pragma unroll
        for (int mt = 0; mt < 2; mt++)
            #pragma unroll
            for (int nt = 0; nt < 4; nt++)
                #pragma unroll
                for (int ci = 0; ci < 4; ci++) {
                    int slot = mt * 2 + (ci >> 1);
                    float e = fexp10s(cacc[mt][nt][ci]);
                    s1[slot] += e;
                    s2[slot] = fmaf(e, e, s2[slot]);
                }

        if (jt + 1 < JT) cpa_wait0();
        __syncthreads();
    }

    #pragma unroll
    for (int slot = 0; slot < 4; slot++) {
        #pragma unroll
        for (int s = 1; s <= 2; s <<= 1) {
            s1[slot] += __shfl_xor_sync(0xffffffffu, s1[slot], s);
            s2[slot] += __shfl_xor_sync(0xffffffffu, s2[slot], s);
        }
    }
    float* red = (float*)smem;   // 4 nwarps * 128 rows * 2 = 4 KB
    if (tg == 0) {
        #pragma unroll
        for (int slot = 0; slot < 4; slot++) {
            int row = wm * 32 + (slot >> 1) * 16 + (slot & 1) * 8 + g;
            int idx = wn * 256 + row * 2;
            red[idx + 0] = s1[slot];
            red[idx + 1] = s2[slot];
        }
    }
    __syncthreads();
    if (tid < 256) {
        int row = tid >> 1, m = tid & 1;
        float v = red[row * 2 + m] + red[256 + row * 2 + m] +
                  red[512 + row * 2 + m] + red[768 + row * 2 + m];
        g_part[((size_t)chunk * N_ROWS + row0 + row) * 2 + m] = v;
    }
}

// ---------------- K_C: fused combine + positives + final ---------------------
__global__ __launch_bounds__(256) void k_post(const long long* __restrict__ tgt,
                                              float* __restrict__ out) {
    const int tid  = threadIdx.x;
    const int w    = (blockIdx.x * 256 + tid) >> 5;
    const int lane = tid & 31;

    // --- combine chunk partials for this row (lanes 0..15 hold chunks) ---
    float a1 = 0.f, a2 = 0.f;
    if (lane < NCHUNK) {
        int base = (lane * N_ROWS + w) * 2;
        a1 = g_part[base + 0];
        a2 = g_part[base + 1];
    }
    #pragma unroll
    for (int s = 8; s; s >>= 1) {
        a1 += __shfl_xor_sync(0xffffffffu, a1, s);
        a2 += __shfl_xor_sync(0xffffffffu, a2, s);
    }
    float S1 = __shfl_sync(0xffffffffu, a1, 0);
    float S2 = __shfl_sync(0xffffffffu, a2, 0);
    if (lane == 0) {
        g_S[w * 2 + 0] = S1;
        g_S[w * 2 + 1] = S2;
    }

    // --- positive pairs (exact exp/log — eps-sensitive path) ---
    long long ci = tgt[w];
    float4 a = *(const float4*)(g_f1 + (size_t)w * DIM + lane * 4);
    float invS1 = 1.0f / S1;

    float L = 0.f, P1 = 0.f, P2 = 0.f;
    int np = 0;
    for (int jb = 0; jb < N_ROWS; jb += 32) {
        unsigned msk = __ballot_sync(0xffffffffu, tgt[jb + lane] == ci);
        np += __popc(msk);
        while (msk) {
            int j = jb + __ffs(msk) - 1;
            msk &= msk - 1;
            float4 b = *(const float4*)(g_f2 + (size_t)j * DIM + lane * 4);
            float d = a.x * b.x + a.y * b.y + a.z * b.z + a.w * b.w;
            #pragma unroll
            for (int s = 16; s; s >>= 1) d += __shfl_xor_sync(0xffffffffu, d, s);
            float e  = __expf((d - 1.0f) * 10.0f);
            float ps = e * invS1;
            L -= __logf(ps + (float)EPSL);
            P1 += ps;
            P2 = fmaf(ps, ps, P2);
        }
    }
    if (lane == 0) {
        g_pos[w * 3 + 0] = L;
        g_pos[w * 3 + 1] = P1;
        g_pos[w * 3 + 2] = P2;
        g_npos[w] = np;
    }

    // --- last-block election; elected block does the deterministic final ---
    __syncthreads();
    __threadfence();
    __shared__ unsigned s_ticket;
    if (tid == 0) s_ticket = atomicAdd(&g_ctr, 1u);
    __syncthreads();
    if (s_ticket != gridDim.x - 1) return;
    __threadfence();

    double nce = 0.0, jsd = 0.0;
    for (int i = tid; i < N_ROWS; i += 256) {
        float fS1 = g_S[i * 2 + 0];
        float fS2 = g_S[i * 2 + 1];
        float fL  = g_pos[i * 3 + 0];
        float fP1 = g_pos[i * 3 + 1];
        float fP2 = g_pos[i * 3 + 2];
        int inp   = g_npos[i];
        float nn  = (float)(N_ROWS - inp);

        float is1 = __fdividef(1.0f, fS1);
        float q1 = 1.0f - fP1;
        float q2 = fS2 * is1 * is1 - fP2;
        float neg = (q1 - nn * (float)EPSL)
                  + 0.5f * (q2 - 2.0f * (float)EPSL * q1);

        nce += (double)(__fdividef(fL, (float)inp) + __fdividef(neg, nn));
        jsd += (double)g_jsd[i];
    }
    __shared__ double shn[256], shj[256];
    shn[tid] = nce;
    shj[tid] = jsd;
    __syncthreads();
    for (int s = 128; s; s >>= 1) {
        if (tid < s) { shn[tid] += shn[tid + s]; shj[tid] += shj[tid + s]; }
        __syncthreads();
    }
    if (tid == 0) {
        out[0] = (float)(shn[0] / (double)N_ROWS + 0.5 * shj[0] / (double)N_ROWS);
        g_ctr = 0;   // reset for next graph replay
    }
}

// ---------------- launch ------------------------------------------------------
extern "C" void kernel_launch(void* const* d_in, const int* in_sizes, int n_in,
                              void* d_out, int out_size) {
    const float*     fs  = (const float*)d_in[0];
    const float*     ft  = (const float*)d_in[1];
    const float*     ls  = (const float*)d_in[2];
    const float*     lt  = (const float*)d_in[3];
    const long long* tgt = (const long long*)d_in[4];

    cudaFuncSetAttribute(k_moments_mma,
                         cudaFuncAttributeMaxDynamicSharedMemorySize, SMEM_GEMM);

    k_prep<<<2048 + N_ROWS, 256>>>(fs, ft, ls, lt);
    k_moments_mma<<<dim3(NCHUNK, N_ROWS / 128), 512, SMEM_GEMM>>>();
    k_post<<<N_ROWS / 8, 256>>>(tgt, (float*)d_out);
}

// round 15
// speedup vs baseline: 7.2025x; 7.2025x over previous
#include <cuda_runtime.h>
#include <cuda_fp16.h>
#include <math.h>
#include <stdint.h>

// ---------------- problem constants ----------------
#define N_ROWS 8192
#define DIM    128
#define NCLS   1000
#define EPSL   1e-10
#define NCHUNK 16               // j-chunks; JT = 4 j-tiles per CTA
#define JT     4

// ---------------- scratch (device globals; no allocations) ------------------
__device__ __align__(16) float   g_f1[N_ROWS * DIM];   // normalized fs (fp32)
__device__ __align__(16) float   g_f2[N_ROWS * DIM];   // normalized ft (fp32)
__device__ __align__(16) __half  g_h1[N_ROWS * DIM];   // fp16 normalized fs
__device__ __align__(16) __half  g_h2[N_ROWS * DIM];   // fp16 normalized ft
__device__ __align__(16) uint8_t g_cls[N_ROWS];        // u8 class per row

__device__ float g_part[NCHUNK * N_ROWS];  // per-chunk S1
__device__ float g_S[N_ROWS];              // combined S1
__device__ float g_pos[N_ROWS * 2];        // L, P1
__device__ int   g_npos[N_ROWS];
__device__ float g_jsd[N_ROWS];
__device__ unsigned g_ctr = 0;             // last-block election counter

// ---------------- fast exp (FMA/ALU pipes only) ------------------------------
__device__ __forceinline__ float fexp2(float y) {
    float z = y + 12582912.0f;
    int   i = __float_as_int(z) - 0x4B400000;
    float f = y - (z - 12582912.0f);
    float p = 0.0013333558f;
    p = fmaf(p, f, 0.0096181291f);
    p = fmaf(p, f, 0.0555041087f);
    p = fmaf(p, f, 0.2402265070f);
    p = fmaf(p, f, 0.6931471806f);
    p = fmaf(p, f, 1.0f);
    return p * __int_as_float((i + 127) << 23);
}
__device__ __forceinline__ float fexp10s(float c) {   // exp((c-1)*10)
    return fexp2(fmaf(c, 14.4269504089f, -14.4269504089f));
}
__device__ __forceinline__ float fexpe(float x) {     // exp(x)
    return fexp2(x * 1.44269504089f);
}

// ---------------- PTX helpers -----------------------------------------------
__device__ __forceinline__ uint32_t smem_u32(const void* p) {
    uint32_t a;
    asm("{ .reg .u64 t; cvta.to.shared.u64 t, %1; cvt.u32.u64 %0, t; }"
        : "=r"(a) : "l"(p));
    return a;
}
__device__ __forceinline__ void cpa16(uint32_t s, const void* g) {
    asm volatile("cp.async.cg.shared.global [%0], [%1], 16;"
                 :: "r"(s), "l"(g) : "memory");
}
__device__ __forceinline__ void cpa_commit() {
    asm volatile("cp.async.commit_group;" ::: "memory");
}
__device__ __forceinline__ void cpa_wait0() {
    asm volatile("cp.async.wait_group 0;" ::: "memory");
}
__device__ __forceinline__ uint32_t lds32(uint32_t a) {
    uint32_t v;
    asm volatile("ld.shared.b32 %0, [%1];" : "=r"(v) : "r"(a));
    return v;
}
__device__ __forceinline__ void mma16816(float c[4], const uint32_t a[4],
                                         const uint32_t b[2]) {
    asm volatile(
        "mma.sync.aligned.m16n8k16.row.col.f32.f16.f16.f32 "
        "{%0,%1,%2,%3}, {%4,%5,%6,%7}, {%8,%9}, {%0,%1,%2,%3};"
        : "+f"(c[0]), "+f"(c[1]), "+f"(c[2]), "+f"(c[3])
        : "r"(a[0]), "r"(a[1]), "r"(a[2]), "r"(a[3]), "r"(b[0]), "r"(b[1]));
}

// ---------------- K_A: normalize | JSD | class-pack ---------------------------
__device__ __forceinline__ void norm_rows(const float* __restrict__ in,
                                          float* __restrict__ fout,
                                          __half* __restrict__ hout,
                                          int w, int lane) {
    float4 v = *(const float4*)(in + (size_t)w * DIM + lane * 4);
    float ss = v.x * v.x + v.y * v.y + v.z * v.z + v.w * v.w;
    #pragma unroll
    for (int s = 16; s; s >>= 1) ss += __shfl_xor_sync(0xffffffffu, ss, s);
    float inv = 1.0f / fmaxf(sqrtf(ss), 1e-12f);
    float x[4] = {v.x * inv, v.y * inv, v.z * inv, v.w * inv};
    *(float4*)(fout + (size_t)w * DIM + lane * 4) = make_float4(x[0], x[1], x[2], x[3]);

    uint32_t p[2] = {0, 0};
    #pragma unroll
    for (int i = 0; i < 4; i++) {
        __half h = __float2half_rn(x[i]);
        p[i >> 1] |= (uint32_t)__half_as_ushort(h) << (16 * (i & 1));
    }
    size_t base = (size_t)w * DIM + lane * 4;
    *(uint2*)((char*)hout + base * 2) = make_uint2(p[0], p[1]);
}

__global__ __launch_bounds__(256) void k_prep(const float* __restrict__ fs,
                                              const float* __restrict__ ft,
                                              const float* __restrict__ ls,
                                              const float* __restrict__ lt,
                                              const long long* __restrict__ tgt) {
    int b = blockIdx.x;
    if (b < 2048) {
        int w    = ((b & 1023) * 256 + threadIdx.x) >> 5;
        int lane = threadIdx.x & 31;
        if (b < 1024) norm_rows(fs, g_f1, g_h1, w, lane);
        else          norm_rows(ft, g_f2, g_h2, w, lane);
        return;
    }
    if (b >= 2048 + N_ROWS) {
        // class-pack: 8 blocks, 4 targets per thread
        int idx = (b - 2048 - N_ROWS) * 1024 + threadIdx.x * 4;
        uchar4 c;
        c.x = (uint8_t)tgt[idx + 0];
        c.y = (uint8_t)tgt[idx + 1];
        c.z = (uint8_t)tgt[idx + 2];
        c.w = (uint8_t)tgt[idx + 3];
        *(uchar4*)(g_cls + idx) = c;
        return;
    }
    // JSD: one block per row, single pass:
    // kl_st + kl_ts = sum (pt - ps)(zt - zs) = U/St - V/Ss
    int r = b - 2048;
    const float* zs = ls + (size_t)r * NCLS;
    const float* zt = lt + (size_t)r * NCLS;
    int tid = threadIdx.x;

    float Ss = 0.f, St = 0.f, U = 0.f, V = 0.f;
    for (int c = tid; c < NCLS; c += 256) {
        float a = zs[c], bb = zt[c];
        float es = fexpe(a), et = fexpe(bb);
        float d = bb - a;
        Ss += es;
        St += et;
        U = fmaf(et, d, U);
        V = fmaf(es, d, V);
    }
    __shared__ float sh[4][8];
    int lane = tid & 31, wid = tid >> 5;
    #pragma unroll
    for (int s = 16; s; s >>= 1) {
        Ss += __shfl_xor_sync(0xffffffffu, Ss, s);
        St += __shfl_xor_sync(0xffffffffu, St, s);
        U  += __shfl_xor_sync(0xffffffffu, U, s);
        V  += __shfl_xor_sync(0xffffffffu, V, s);
    }
    if (lane == 0) { sh[0][wid] = Ss; sh[1][wid] = St; sh[2][wid] = U; sh[3][wid] = V; }
    __syncthreads();
    if (tid == 0) {
        float ss2 = 0.f, st2 = 0.f, u2 = 0.f, v2 = 0.f;
        #pragma unroll
        for (int i = 0; i < 8; i++) {
            ss2 += sh[0][i]; st2 += sh[1][i]; u2 += sh[2][i]; v2 += sh[3][i];
        }
        g_jsd[r] = __fdividef(u2, st2) - __fdividef(v2, ss2);
    }
}

// ---------------- K_B: fp16 mma.sync GEMM, XOR smem, S1-only epilogue --------
#define BUF_T  32768                     // bytes per XOR-swizzled 128x128 fp16 tile
#define SM_A   0
#define SM_B(s) (BUF_T + (s) * BUF_T)
#define SMEM_GEMM (3 * BUF_T)            // 98304 = 96 KB -> 2 CTA/SM

// XOR tile: addr(r, chunk) = r*256 + ((chunk&8) | ((chunk&7)^(r&7)))*16
__device__ __forceinline__ void load_tile(uint32_t sdst, const char* gsrc, int tid) {
    #pragma unroll
    for (int i = 0; i < 4; i++) {
        int flat = tid + i * 512;
        int r = flat >> 4, gI = flat & 15;
        int blk = (gI & 8) | ((gI & 7) ^ (r & 7));
        cpa16(sdst + r * 256 + blk * 16, gsrc + r * 256 + gI * 16);
    }
}

__global__ __launch_bounds__(512, 2) void k_moments_mma() {
    extern __shared__ __align__(16) char smem[];
    const int tid  = threadIdx.x;
    const int warp = tid >> 5, lane = tid & 31;
    const int g    = lane >> 2, tg = lane & 3;
    const int wm   = warp >> 2, wn = warp & 3;
    const int row0 = blockIdx.y * 128;
    const int chunk = blockIdx.x;

    const uint32_t sb = smem_u32(smem);

    {
        int t0 = chunk * JT;
        load_tile(sb + SM_A, (const char*)g_h1 + (size_t)row0 * 256, tid);
        load_tile(sb + SM_B(0), (const char*)g_h2 + (size_t)t0 * 32768, tid);
        cpa_commit();
        cpa_wait0();
    }
    __syncthreads();

    // per-thread row bases (XOR column-block added per k-step)
    const uint32_t aR = sb + SM_A + (uint32_t)(wm * 32 + g) * 256 + tg * 4;
    const uint32_t bR0 = (uint32_t)(wn * 32 + g) * 256 + tg * 4;

    float s1[4] = {0, 0, 0, 0};

    for (int jt = 0; jt < JT; jt++) {
        const int cur = jt & 1;
        if (jt + 1 < JT) {
            int tn = chunk * JT + jt + 1;
            load_tile(sb + SM_B(1 - cur), (const char*)g_h2 + (size_t)tn * 32768, tid);
            cpa_commit();
        }

        float cacc[2][4][4];
        #pragma unroll
        for (int mt = 0; mt < 2; mt++)
            #pragma unroll
            for (int nt = 0; nt < 4; nt++)
                #pragma unroll
                for (int ci = 0; ci < 4; ci++) cacc[mt][nt][ci] = 0.f;

        const uint32_t bR = sb + SM_B(cur) + bR0;

        #pragma unroll
        for (int ks = 0; ks < 8; ks++) {
            const int c0 = 2 * ks, c1 = 2 * ks + 1;
            const uint32_t cb0 = (uint32_t)(((c0 & 8) | ((c0 & 7) ^ g))) << 4;
            const uint32_t cb1 = (uint32_t)(((c1 & 8) | ((c1 & 7) ^ g))) << 4;
            uint32_t af[2][4], bf[4][2];
            #pragma unroll
            for (int mt = 0; mt < 2; mt++) {
                uint32_t ro = aR + mt * 4096;
                af[mt][0] = lds32(ro + cb0);
                af[mt][1] = lds32(ro + 2048 + cb0);
                af[mt][2] = lds32(ro + cb1);
                af[mt][3] = lds32(ro + 2048 + cb1);
            }
            #pragma unroll
            for (int nt = 0; nt < 4; nt++) {
                uint32_t no = bR + nt * 2048;
                bf[nt][0] = lds32(no + cb0);
                bf[nt][1] = lds32(no + cb1);
            }
            #pragma unroll
            for (int mt = 0; mt < 2; mt++)
                #pragma unroll
                for (int nt = 0; nt < 4; nt++)
                    mma16816(cacc[mt][nt], af[mt], bf[nt]);
        }

        // fused epilogue: S1 only
        #pragma unroll
        for (int mt = 0; mt < 2; mt++)
            #pragma unroll
            for (int nt = 0; nt < 4; nt++)
                #pragma unroll
                for (int ci = 0; ci < 4; ci++)
                    s1[mt * 2 + (ci >> 1)] += fexp10s(cacc[mt][nt][ci]);

        if (jt + 1 < JT) cpa_wait0();
        __syncthreads();
    }

    #pragma unroll
    for (int slot = 0; slot < 4; slot++) {
        #pragma unroll
        for (int s = 1; s <= 2; s <<= 1)
            s1[slot] += __shfl_xor_sync(0xffffffffu, s1[slot], s);
    }
    float* red = (float*)smem;   // 4 * 128 floats = 2 KB
    if (tg == 0) {
        #pragma unroll
        for (int slot = 0; slot < 4; slot++) {
            int row = wm * 32 + (slot >> 1) * 16 + (slot & 1) * 8 + g;
            red[wn * 128 + row] = s1[slot];
        }
    }
    __syncthreads();
    if (tid < 128)
        g_part[(size_t)chunk * N_ROWS + row0 + tid] =
            red[tid] + red[128 + tid] + red[256 + tid] + red[384 + tid];
}

// ---------------- K_C: combine + positives (smem class scan) + final ---------
__global__ __launch_bounds__(256) void k_post(float* __restrict__ out) {
    __shared__ __align__(16) uint8_t s_cls[N_ROWS];   // 16B-aligned: uint4 copies
    __shared__ uint16_t s_list[8][320];

    const int tid  = threadIdx.x;
    const int wl   = tid >> 5;               // warp in block 0..7
    const int lane = tid & 31;
    const int w    = blockIdx.x * 8 + wl;    // row

    // load class array into smem (8 KB)
    {
        const uint4* src = (const uint4*)g_cls;
        uint4* dst = (uint4*)s_cls;
        dst[tid]       = src[tid];
        dst[tid + 256] = src[tid + 256];
    }
    __syncthreads();

    // --- combine chunk partials (S1) ---
    float a1 = (lane < NCHUNK) ? g_part[lane * N_ROWS + w] : 0.f;
    #pragma unroll
    for (int s = 8; s; s >>= 1) a1 += __shfl_xor_sync(0xffffffffu, a1, s);
    float S1 = __shfl_sync(0xffffffffu, a1, 0);
    if (lane == 0) g_S[w] = S1;

    // --- build positive j-list via vectorized class scan ---
    uint32_t ci4 = (uint32_t)s_cls[w] * 0x01010101u;
    const uint32_t* cls32 = (const uint32_t*)s_cls;
    int np = 0;
    for (int jb = 0; jb < N_ROWS; jb += 128) {
        uint32_t p  = cls32[(jb >> 2) + lane];
        uint32_t eq = __vcmpeq4(p, ci4);
        #pragma unroll
        for (int b = 0; b < 4; b++) {
            uint32_t bit = (eq >> (8 * b)) & 1u;
            uint32_t msk = __ballot_sync(0xffffffffu, bit);
            if (bit) {
                int idx = np + __popc(msk & ((1u << lane) - 1u));
                if (idx < 320)
                    s_list[wl][idx] = (uint16_t)(jb + lane * 4 + b);
            }
            np += __popc(msk);
        }
    }
    if (np > 320) np = 320;   // defensive (cannot trigger: max class count ~120)
    __syncwarp();

    // --- positives: 2-way interleaved exact exp/log ---
    float4 a = *(const float4*)(g_f1 + (size_t)w * DIM + lane * 4);
    float invS1 = 1.0f / S1;
    float L = 0.f, P1 = 0.f;
    int i = 0;
    for (; i + 1 < np; i += 2) {
        int j0 = s_list[wl][i], j1 = s_list[wl][i + 1];
        float4 b0 = *(const float4*)(g_f2 + (size_t)j0 * DIM + lane * 4);
        float4 b1 = *(const float4*)(g_f2 + (size_t)j1 * DIM + lane * 4);
        float d0 = a.x * b0.x + a.y * b0.y + a.z * b0.z + a.w * b0.w;
        float d1 = a.x * b1.x + a.y * b1.y + a.z * b1.z + a.w * b1.w;
        #pragma unroll
        for (int s = 16; s; s >>= 1) {
            d0 += __shfl_xor_sync(0xffffffffu, d0, s);
            d1 += __shfl_xor_sync(0xffffffffu, d1, s);
        }
        float ps0 = __expf((d0 - 1.0f) * 10.0f) * invS1;
        float ps1 = __expf((d1 - 1.0f) * 10.0f) * invS1;
        L -= __logf(ps0 + (float)EPSL) + __logf(ps1 + (float)EPSL);
        P1 += ps0 + ps1;
    }
    if (i < np) {
        int j0 = s_list[wl][i];
        float4 b0 = *(const float4*)(g_f2 + (size_t)j0 * DIM + lane * 4);
        float d0 = a.x * b0.x + a.y * b0.y + a.z * b0.z + a.w * b0.w;
        #pragma unroll
        for (int s = 16; s; s >>= 1) d0 += __shfl_xor_sync(0xffffffffu, d0, s);
        float ps0 = __expf((d0 - 1.0f) * 10.0f) * invS1;
        L -= __logf(ps0 + (float)EPSL);
        P1 += ps0;
    }
    if (lane == 0) {
        g_pos[w * 2 + 0] = L;
        g_pos[w * 2 + 1] = P1;
        g_npos[w] = np;
    }

    // --- last-block election; elected block does the deterministic final ---
    __syncthreads();
    __threadfence();
    __shared__ unsigned s_ticket;
    if (tid == 0) s_ticket = atomicAdd(&g_ctr, 1u);
    __syncthreads();
    if (s_ticket != gridDim.x - 1) return;
    __threadfence();

    double nce = 0.0, jsd = 0.0;
    for (int r = tid; r < N_ROWS; r += 256) {
        float fL  = g_pos[r * 2 + 0];
        float fP1 = g_pos[r * 2 + 1];
        int inp   = g_npos[r];
        float nn  = (float)(N_ROWS - inp);
        float neg = (1.0f - fP1) - nn * (float)EPSL;   // sum_neg -log(1-ps+eps), 1st order
        nce += (double)(__fdividef(fL, (float)inp) + __fdividef(neg, nn));
        jsd += (double)g_jsd[r];
    }
    __shared__ double shn[256], shj[256];
    shn[tid] = nce;
    shj[tid] = jsd;
    __syncthreads();
    for (int s = 128; s; s >>= 1) {
        if (tid < s) { shn[tid] += shn[tid + s]; shj[tid] += shj[tid + s]; }
        __syncthreads();
    }
    if (tid == 0) {
        out[0] = (float)(shn[0] / (double)N_ROWS + 0.5 * shj[0] / (double)N_ROWS);
        g_ctr = 0;
    }
}

// ---------------- launch ------------------------------------------------------
extern "C" void kernel_launch(void* const* d_in, const int* in_sizes, int n_in,
                              void* d_out, int out_size) {
    const float*     fs  = (const float*)d_in[0];
    const float*     ft  = (const float*)d_in[1];
    const float*     ls  = (const float*)d_in[2];
    const float*     lt  = (const float*)d_in[3];
    const long long* tgt = (const long long*)d_in[4];

    cudaFuncSetAttribute(k_moments_mma,
                         cudaFuncAttributeMaxDynamicSharedMemorySize, SMEM_GEMM);

    k_prep<<<2048 + N_ROWS + 8, 256>>>(fs, ft, ls, lt, tgt);
    k_moments_mma<<<dim3(NCHUNK, N_ROWS / 128), 512, SMEM_GEMM>>>();
    k_post<<<N_ROWS / 8, 256>>>((float*)d_out);
}